// round 2
// baseline (speedup 1.0000x reference)
#include <cuda_runtime.h>
#include <math_constants.h>

// Problem constants
static constexpr int B_ = 4;
static constexpr int T_ = 4096;
static constexpr int D_ = 1024;
static constexpr int H_ = 64;
static constexpr int BT = B_ * T_;

// Scratch for Q, K, V projections (device globals: allocation-free per harness rules)
__device__ float g_Q[BT * H_];
__device__ float g_K[BT * H_];
__device__ float g_V[BT * H_];

// ---------------------------------------------------------------------------
// Projection kernel: Q|K|V = x @ Wq|Wk|Wv
// Block: 64 rows of x, 256 threads. d processed in chunks of 32.
// Thread (rowg, colg) computes a 4x4 micro-tile for each of the 3 outputs.
// ---------------------------------------------------------------------------
__global__ void __launch_bounds__(256, 1) proj_kernel(
    const float* __restrict__ x,
    const float* __restrict__ Wq,
    const float* __restrict__ Wk,
    const float* __restrict__ Wv)
{
    __shared__ float Xs[64][33];        // 64 rows x 32 d (+1 pad to kill bank conflicts)
    __shared__ float Wsq[32][64];
    __shared__ float Wsk[32][64];
    __shared__ float Wsv[32][64];

    const int tid = threadIdx.x;
    const int rowg = tid >> 4;    // 0..15  (4 rows each)
    const int colg = tid & 15;    // 0..15  (4 h-cols each)
    const int rowbase = blockIdx.x * 64;

    float accq[4][4];
    float acck[4][4];
    float accv[4][4];
#pragma unroll
    for (int i = 0; i < 4; i++)
#pragma unroll
        for (int j = 0; j < 4; j++) {
            accq[i][j] = 0.f; acck[i][j] = 0.f; accv[i][j] = 0.f;
        }

    for (int dbase = 0; dbase < D_; dbase += 32) {
        // Load X tile: 64 rows x 32 d
        for (int t = tid; t < 64 * 32; t += 256) {
            int r = t >> 5;
            int d = t & 31;
            Xs[r][d] = x[(size_t)(rowbase + r) * D_ + dbase + d];
        }
        // Load W tiles: 32 d x 64 h, three matrices
        for (int t = tid; t < 32 * 64; t += 256) {
            int d = t >> 6;
            int h = t & 63;
            size_t gi = (size_t)(dbase + d) * H_ + h;
            Wsq[d][h] = Wq[gi];
            Wsk[d][h] = Wk[gi];
            Wsv[d][h] = Wv[gi];
        }
        __syncthreads();

#pragma unroll 8
        for (int d = 0; d < 32; d++) {
            float xr[4];
#pragma unroll
            for (int i = 0; i < 4; i++) xr[i] = Xs[rowg * 4 + i][d];
            float4 wq = *reinterpret_cast<const float4*>(&Wsq[d][colg * 4]);
            float4 wk = *reinterpret_cast<const float4*>(&Wsk[d][colg * 4]);
            float4 wv = *reinterpret_cast<const float4*>(&Wsv[d][colg * 4]);
#pragma unroll
            for (int i = 0; i < 4; i++) {
                accq[i][0] += xr[i] * wq.x; accq[i][1] += xr[i] * wq.y;
                accq[i][2] += xr[i] * wq.z; accq[i][3] += xr[i] * wq.w;
                acck[i][0] += xr[i] * wk.x; acck[i][1] += xr[i] * wk.y;
                acck[i][2] += xr[i] * wk.z; acck[i][3] += xr[i] * wk.w;
                accv[i][0] += xr[i] * wv.x; accv[i][1] += xr[i] * wv.y;
                accv[i][2] += xr[i] * wv.z; accv[i][3] += xr[i] * wv.w;
            }
        }
        __syncthreads();
    }

#pragma unroll
    for (int i = 0; i < 4; i++) {
        int r = rowbase + rowg * 4 + i;
#pragma unroll
        for (int j = 0; j < 4; j++) {
            int h = colg * 4 + j;
            g_Q[(size_t)r * H_ + h] = accq[i][j];
            g_K[(size_t)r * H_ + h] = acck[i][j];
            g_V[(size_t)r * H_ + h] = accv[i][j];
        }
    }
}

// ---------------------------------------------------------------------------
// Flash attention kernel (causal), fp32.
// Block: 64 query rows, 128 threads -> 2 threads per query row (split dims 32/32).
// Streams K/V in 64-key shared tiles with online softmax.
// UNIFORM trip counts everywhere: the diagonal tile masks out-of-causal keys
// with s = -inf instead of shortening the loop (keeps warps converged for
// the full-mask shfl — divergent exit there deadlocks on sm_103a).
// Heavy blocks (high qt) launched first to balance the causal triangle.
// ---------------------------------------------------------------------------
__global__ void __launch_bounds__(128, 1) attn_kernel(float* __restrict__ out)
{
    __shared__ float Ks[64][64];
    __shared__ float Vs[64][64];

    const int tid = threadIdx.x;
    const int row = tid >> 1;       // 0..63
    const int half = tid & 1;       // which 32-dim half this thread owns
    const int qt = gridDim.x - 1 - blockIdx.x;   // reverse order: heavy first
    const int b = blockIdx.y;
    const int q_global = qt * 64 + row;
    const size_t qrow = (size_t)(b * T_ + q_global) * H_;

    // Load this thread's half of q into registers
    float qreg[32];
    {
        const float4* qp = reinterpret_cast<const float4*>(&g_Q[qrow + half * 32]);
#pragma unroll
        for (int i = 0; i < 8; i++) {
            float4 v = qp[i];
            qreg[i * 4 + 0] = v.x; qreg[i * 4 + 1] = v.y;
            qreg[i * 4 + 2] = v.z; qreg[i * 4 + 3] = v.w;
        }
    }

    float m = -CUDART_INF_F;
    float l = 0.f;
    float acc[32];
#pragma unroll
    for (int i = 0; i < 32; i++) acc[i] = 0.f;

    const float scale = 0.125f;   // 1/sqrt(64)
    const int ntiles = qt + 1;

    for (int kt = 0; kt < ntiles; kt++) {
        const int kbase = kt * 64;
        const bool diag = (kt == qt);   // uniform across the block
        // Cooperative load of K and V tiles (64 keys x 64 dims, float4)
        {
            const size_t gbase = (size_t)(b * T_ + kbase) * H_;
            for (int t = tid * 4; t < 64 * 64; t += 128 * 4) {
                int key = t >> 6;
                int d = t & 63;
                *reinterpret_cast<float4*>(&Ks[key][d]) =
                    *reinterpret_cast<const float4*>(&g_K[gbase + (size_t)key * H_ + d]);
                *reinterpret_cast<float4*>(&Vs[key][d]) =
                    *reinterpret_cast<const float4*>(&g_V[gbase + (size_t)key * H_ + d]);
            }
        }
        __syncthreads();

        // Uniform 64-iteration loop: every lane runs every j.
        for (int j = 0; j < 64; j++) {
            const float* kr = &Ks[j][half * 32];
            float s0 = 0.f, s1 = 0.f, s2 = 0.f, s3 = 0.f;
#pragma unroll
            for (int i = 0; i < 32; i += 4) {
                s0 += qreg[i + 0] * kr[i + 0];
                s1 += qreg[i + 1] * kr[i + 1];
                s2 += qreg[i + 2] * kr[i + 2];
                s3 += qreg[i + 3] * kr[i + 3];
            }
            float s = (s0 + s1) + (s2 + s3);
            s += __shfl_xor_sync(0xffffffffu, s, 1);   // all lanes converged
            s *= scale;
            if (diag && (kbase + j > q_global)) s = -CUDART_INF_F;  // causal mask

            float mn = fmaxf(m, s);
            if (mn > m) {
                float c = __expf(m - mn);   // expf(-inf)=0 handles first key
                l *= c;
#pragma unroll
                for (int i = 0; i < 32; i++) acc[i] *= c;
                m = mn;
            }
            float p = __expf(s - m);        // masked keys: p = 0
            l += p;
            const float* vr = &Vs[j][half * 32];
#pragma unroll
            for (int i = 0; i < 32; i++) acc[i] += p * vr[i];
        }
        __syncthreads();
    }

    const float inv = 1.f / l;
    float* op = &out[qrow + half * 32];
#pragma unroll
    for (int i = 0; i < 32; i++) op[i] = acc[i] * inv;
}

// ---------------------------------------------------------------------------
extern "C" void kernel_launch(void* const* d_in, const int* in_sizes, int n_in,
                              void* d_out, int out_size)
{
    const float* x  = (const float*)d_in[0];
    const float* Wq = (const float*)d_in[1];
    const float* Wk = (const float*)d_in[2];
    const float* Wv = (const float*)d_in[3];
    float* out = (float*)d_out;

    proj_kernel<<<BT / 64, 256>>>(x, Wq, Wk, Wv);
    attn_kernel<<<dim3(T_ / 64, B_), 128>>>(out);
}

// round 3
// speedup vs baseline: 5.3097x; 5.3097x over previous
#include <cuda_runtime.h>
#include <math_constants.h>

// Problem constants
static constexpr int B_ = 4;
static constexpr int T_ = 4096;
static constexpr int D_ = 1024;
static constexpr int H_ = 64;
static constexpr int BT = B_ * T_;

// Scratch for Q, K, V projections (device globals: allocation-free per harness rules)
__device__ float g_Q[BT * H_];
__device__ float g_K[BT * H_];
__device__ float g_V[BT * H_];

// ---------------------------------------------------------------------------
// tf32 helpers
// ---------------------------------------------------------------------------
__device__ __forceinline__ unsigned f2tf(float f) {
    unsigned u;
    asm("cvt.rna.tf32.f32 %0, %1;" : "=r"(u) : "f"(f));
    return u;
}

// D = A(16x8) * B(8x8) + D, tf32 inputs, fp32 accumulate.
__device__ __forceinline__ void mma_tf32(float* d, const unsigned* a, const unsigned* b) {
    asm volatile(
        "mma.sync.aligned.m16n8k8.row.col.f32.tf32.tf32.f32 "
        "{%0,%1,%2,%3}, {%4,%5,%6,%7}, {%8,%9}, {%0,%1,%2,%3};"
        : "+f"(d[0]), "+f"(d[1]), "+f"(d[2]), "+f"(d[3])
        : "r"(a[0]), "r"(a[1]), "r"(a[2]), "r"(a[3]), "r"(b[0]), "r"(b[1]));
}

// ---------------------------------------------------------------------------
// Projection kernel (tensor cores): Q|K|V = x @ Wq|Wk|Wv
// Block: 128 rows, 256 threads (8 warps), each warp owns 16 rows x 64 cols
// for all three outputs. K processed in 32-wide chunks.
// Fragment conventions (m16n8k8): g = lane>>2 (group), c = lane&3.
//   A: a0=(g,c) a1=(g+8,c) a2=(g,c+4) a3=(g+8,c+4)        [row, k]
//   B: b0=(k=c, n=g) b1=(k=c+4, n=g)                       col-major
//   C: c0=(g,2c) c1=(g,2c+1) c2=(g+8,2c) c3=(g+8,2c+1)
// ---------------------------------------------------------------------------
__global__ void __launch_bounds__(256, 1) proj_kernel(
    const float* __restrict__ x,
    const float* __restrict__ Wq,
    const float* __restrict__ Wk,
    const float* __restrict__ Wv)
{
    __shared__ unsigned Xs[128][40];     // stride 40: A-frag banks 8g+c, conflict-free
    __shared__ unsigned Ws[3][32][72];   // stride 72: B-frag banks 8c+g, conflict-free

    const int tid = threadIdx.x;
    const int lane = tid & 31;
    const int warp = tid >> 5;
    const int g = lane >> 2;
    const int c = lane & 3;
    const int wrow = warp * 16;
    const int rowbase = blockIdx.x * 128;

    const float* Wp0 = Wq;
    const float* Wp1 = Wk;
    const float* Wp2 = Wv;

    float acc[3][8][4];
#pragma unroll
    for (int w = 0; w < 3; w++)
#pragma unroll
        for (int n = 0; n < 8; n++)
#pragma unroll
            for (int i = 0; i < 4; i++) acc[w][n][i] = 0.f;

    for (int kb = 0; kb < D_; kb += 32) {
        // Load X tile: 128 rows x 32 k  (1024 float4)
#pragma unroll
        for (int t = tid; t < 1024; t += 256) {
            int r = t >> 3, q4 = t & 7;
            float4 v = *reinterpret_cast<const float4*>(
                &x[(size_t)(rowbase + r) * D_ + kb + q4 * 4]);
            unsigned* dst = &Xs[r][q4 * 4];
            dst[0] = f2tf(v.x); dst[1] = f2tf(v.y);
            dst[2] = f2tf(v.z); dst[3] = f2tf(v.w);
        }
        // Load W tiles: 3 x (32 x 64)  (1536 float4)
#pragma unroll
        for (int t = tid; t < 1536; t += 256) {
            int w = t >> 9;            // /512
            int r = (t >> 4) & 31;
            int q4 = t & 15;
            const float* Wsrc = (w == 0) ? Wp0 : (w == 1) ? Wp1 : Wp2;
            float4 v = *reinterpret_cast<const float4*>(
                &Wsrc[(size_t)(kb + r) * H_ + q4 * 4]);
            unsigned* dst = &Ws[w][r][q4 * 4];
            dst[0] = f2tf(v.x); dst[1] = f2tf(v.y);
            dst[2] = f2tf(v.z); dst[3] = f2tf(v.w);
        }
        __syncthreads();

#pragma unroll
        for (int k8 = 0; k8 < 4; k8++) {
            unsigned a[4];
            a[0] = Xs[wrow + g][k8 * 8 + c];
            a[1] = Xs[wrow + g + 8][k8 * 8 + c];
            a[2] = Xs[wrow + g][k8 * 8 + c + 4];
            a[3] = Xs[wrow + g + 8][k8 * 8 + c + 4];
#pragma unroll
            for (int w = 0; w < 3; w++)
#pragma unroll
                for (int n = 0; n < 8; n++) {
                    unsigned b[2] = { Ws[w][k8 * 8 + c][n * 8 + g],
                                      Ws[w][k8 * 8 + c + 4][n * 8 + g] };
                    mma_tf32(acc[w][n], a, b);
                }
        }
        __syncthreads();
    }

    // Epilogue: write Q/K/V
#pragma unroll
    for (int n = 0; n < 8; n++) {
        size_t i0 = (size_t)(rowbase + wrow + g) * H_ + n * 8 + 2 * c;
        size_t i1 = i0 + (size_t)8 * H_;
        *reinterpret_cast<float2*>(&g_Q[i0]) = make_float2(acc[0][n][0], acc[0][n][1]);
        *reinterpret_cast<float2*>(&g_Q[i1]) = make_float2(acc[0][n][2], acc[0][n][3]);
        *reinterpret_cast<float2*>(&g_K[i0]) = make_float2(acc[1][n][0], acc[1][n][1]);
        *reinterpret_cast<float2*>(&g_K[i1]) = make_float2(acc[1][n][2], acc[1][n][3]);
        *reinterpret_cast<float2*>(&g_V[i0]) = make_float2(acc[2][n][0], acc[2][n][1]);
        *reinterpret_cast<float2*>(&g_V[i1]) = make_float2(acc[2][n][2], acc[2][n][3]);
    }
}

// ---------------------------------------------------------------------------
// Flash attention kernel (causal), tf32 tensor cores, FA2 style.
// Block: 64 queries, 128 threads (4 warps), each warp owns 16 query rows.
// Per key tile (64 keys):
//   S = Q K^T  via mma (K smem tile read row-major = col-major B operand)
//   fragment-level online softmax (quad shfl reductions)
//   P -> smem (reusing K buffer) to convert C-frag layout to A-frag layout
//   O += P V   via mma
// ---------------------------------------------------------------------------
__global__ void __launch_bounds__(128, 2) attn_kernel(float* __restrict__ out)
{
    __shared__ unsigned KP[64][68];  // K tile during S phase, then P; Q staging at start
    __shared__ unsigned Vs[64][72];

    const int tid = threadIdx.x;
    const int lane = tid & 31;
    const int warp = tid >> 5;
    const int g = lane >> 2;
    const int c = lane & 3;
    const int wrow = warp * 16;
    const int qt = gridDim.x - 1 - blockIdx.x;   // heavy blocks first
    const int b = blockIdx.y;
    const int q0 = qt * 64;
    const size_t qbase = (size_t)(b * T_ + q0) * H_;

    // Stage Q (pre-scaled by 1/sqrt(64)) into KP, then pull A-fragments.
#pragma unroll
    for (int t = tid; t < 1024; t += 128) {       // 64 rows x 16 float4
        int r = t >> 4, q4 = t & 15;
        float4 v = *reinterpret_cast<const float4*>(&g_Q[qbase + (size_t)r * H_ + q4 * 4]);
        unsigned* dst = &KP[r][q4 * 4];
        dst[0] = f2tf(v.x * 0.125f); dst[1] = f2tf(v.y * 0.125f);
        dst[2] = f2tf(v.z * 0.125f); dst[3] = f2tf(v.w * 0.125f);
    }
    __syncthreads();

    unsigned qa[8][4];
#pragma unroll
    for (int k8 = 0; k8 < 8; k8++) {
        qa[k8][0] = KP[wrow + g][k8 * 8 + c];
        qa[k8][1] = KP[wrow + g + 8][k8 * 8 + c];
        qa[k8][2] = KP[wrow + g][k8 * 8 + c + 4];
        qa[k8][3] = KP[wrow + g + 8][k8 * 8 + c + 4];
    }

    float o[8][4];
#pragma unroll
    for (int n = 0; n < 8; n++)
#pragma unroll
        for (int i = 0; i < 4; i++) o[n][i] = 0.f;
    float m0 = -CUDART_INF_F, m1 = -CUDART_INF_F;
    float l0 = 0.f, l1 = 0.f;

    for (int kt = 0; kt <= qt; kt++) {
        __syncthreads();   // previous tile's PV / Q-frag reads done before overwrite
        const int kb = kt * 64;
        const size_t kvbase = (size_t)(b * T_ + kb) * H_;

        // Load K and V tiles (64 x 64 each), converting to tf32.
#pragma unroll
        for (int t = tid; t < 1024; t += 128) {
            int r = t >> 4, q4 = t & 15;
            float4 kv = *reinterpret_cast<const float4*>(&g_K[kvbase + (size_t)r * H_ + q4 * 4]);
            unsigned* kd = &KP[r][q4 * 4];
            kd[0] = f2tf(kv.x); kd[1] = f2tf(kv.y); kd[2] = f2tf(kv.z); kd[3] = f2tf(kv.w);
            float4 vv = *reinterpret_cast<const float4*>(&g_V[kvbase + (size_t)r * H_ + q4 * 4]);
            unsigned* vd = &Vs[r][q4 * 4];
            vd[0] = f2tf(vv.x); vd[1] = f2tf(vv.y); vd[2] = f2tf(vv.z); vd[3] = f2tf(vv.w);
        }
        __syncthreads();

        // S = Q K^T : B operand (k=dim, n=key) read from row-major K tile.
        float s[8][4];
#pragma unroll
        for (int n = 0; n < 8; n++)
#pragma unroll
            for (int i = 0; i < 4; i++) s[n][i] = 0.f;
#pragma unroll
        for (int k8 = 0; k8 < 8; k8++)
#pragma unroll
            for (int n = 0; n < 8; n++) {
                unsigned bfr[2] = { KP[n * 8 + g][k8 * 8 + c],
                                    KP[n * 8 + g][k8 * 8 + c + 4] };
                mma_tf32(s[n], qa[k8], bfr);
            }
        __syncthreads();   // K fully consumed by all warps; KP now reusable for P

        // Causal mask (diagonal tile only)
        if (kt == qt) {
            const int r0 = q0 + wrow + g;
#pragma unroll
            for (int n = 0; n < 8; n++) {
                int col = kb + n * 8 + 2 * c;
                if (col     > r0)     s[n][0] = -CUDART_INF_F;
                if (col + 1 > r0)     s[n][1] = -CUDART_INF_F;
                if (col     > r0 + 8) s[n][2] = -CUDART_INF_F;
                if (col + 1 > r0 + 8) s[n][3] = -CUDART_INF_F;
            }
        }

        // Row max (across n-tiles then across the 4 threads of each row quad)
        float mx0 = -CUDART_INF_F, mx1 = -CUDART_INF_F;
#pragma unroll
        for (int n = 0; n < 8; n++) {
            mx0 = fmaxf(mx0, fmaxf(s[n][0], s[n][1]));
            mx1 = fmaxf(mx1, fmaxf(s[n][2], s[n][3]));
        }
        mx0 = fmaxf(mx0, __shfl_xor_sync(0xffffffffu, mx0, 1));
        mx0 = fmaxf(mx0, __shfl_xor_sync(0xffffffffu, mx0, 2));
        mx1 = fmaxf(mx1, __shfl_xor_sync(0xffffffffu, mx1, 1));
        mx1 = fmaxf(mx1, __shfl_xor_sync(0xffffffffu, mx1, 2));

        const float mn0 = fmaxf(m0, mx0);
        const float mn1 = fmaxf(m1, mx1);
        const float al0 = __expf(m0 - mn0);   // exp(-inf)=0 on first tile
        const float al1 = __expf(m1 - mn1);

        float sum0 = 0.f, sum1 = 0.f;
#pragma unroll
        for (int n = 0; n < 8; n++) {
            float p00 = __expf(s[n][0] - mn0);
            float p01 = __expf(s[n][1] - mn0);
            float p10 = __expf(s[n][2] - mn1);
            float p11 = __expf(s[n][3] - mn1);
            sum0 += p00 + p01;
            sum1 += p10 + p11;
            uint2 u0; u0.x = f2tf(p00); u0.y = f2tf(p01);
            *reinterpret_cast<uint2*>(&KP[wrow + g][n * 8 + 2 * c]) = u0;
            uint2 u1; u1.x = f2tf(p10); u1.y = f2tf(p11);
            *reinterpret_cast<uint2*>(&KP[wrow + g + 8][n * 8 + 2 * c]) = u1;
            o[n][0] *= al0; o[n][1] *= al0;
            o[n][2] *= al1; o[n][3] *= al1;
        }
        sum0 += __shfl_xor_sync(0xffffffffu, sum0, 1);
        sum0 += __shfl_xor_sync(0xffffffffu, sum0, 2);
        sum1 += __shfl_xor_sync(0xffffffffu, sum1, 1);
        sum1 += __shfl_xor_sync(0xffffffffu, sum1, 2);
        l0 = l0 * al0 + sum0;
        l1 = l1 * al1 + sum1;
        m0 = mn0;
        m1 = mn1;
        __syncwarp();      // P stores visible to all lanes of this warp

        // O += P V  (P rows are warp-private in KP)
#pragma unroll
        for (int k8 = 0; k8 < 8; k8++) {
            unsigned a[4];
            a[0] = KP[wrow + g][k8 * 8 + c];
            a[1] = KP[wrow + g + 8][k8 * 8 + c];
            a[2] = KP[wrow + g][k8 * 8 + c + 4];
            a[3] = KP[wrow + g + 8][k8 * 8 + c + 4];
#pragma unroll
            for (int n = 0; n < 8; n++) {
                unsigned bfr[2] = { Vs[k8 * 8 + c][n * 8 + g],
                                    Vs[k8 * 8 + c + 4][n * 8 + g] };
                mma_tf32(o[n], a, bfr);
            }
        }
    }

    // Epilogue
    const float inv0 = 1.f / l0;
    const float inv1 = 1.f / l1;
#pragma unroll
    for (int n = 0; n < 8; n++) {
        size_t i0 = qbase + (size_t)(wrow + g) * H_ + n * 8 + 2 * c;
        size_t i1 = i0 + (size_t)8 * H_;
        *reinterpret_cast<float2*>(&out[i0]) = make_float2(o[n][0] * inv0, o[n][1] * inv0);
        *reinterpret_cast<float2*>(&out[i1]) = make_float2(o[n][2] * inv1, o[n][3] * inv1);
    }
}

// ---------------------------------------------------------------------------
extern "C" void kernel_launch(void* const* d_in, const int* in_sizes, int n_in,
                              void* d_out, int out_size)
{
    const float* x  = (const float*)d_in[0];
    const float* Wq = (const float*)d_in[1];
    const float* Wk = (const float*)d_in[2];
    const float* Wv = (const float*)d_in[3];
    float* out = (float*)d_out;

    proj_kernel<<<BT / 128, 256>>>(x, Wq, Wk, Wv);
    attn_kernel<<<dim3(T_ / 64, B_), 128>>>(out);
}

// round 4
// speedup vs baseline: 5.9826x; 1.1267x over previous
#include <cuda_runtime.h>
#include <math_constants.h>

// Problem constants
static constexpr int B_ = 4;
static constexpr int T_ = 4096;
static constexpr int D_ = 1024;
static constexpr int H_ = 64;
static constexpr int BT = B_ * T_;

// Scratch (device globals: allocation-free per harness rules)
__device__ float g_Q[BT * H_];   // pre-scaled by 0.125 and tf32-rounded
__device__ float g_K[BT * H_];   // tf32-rounded
__device__ float g_V[BT * H_];   // tf32-rounded

// Split-K attention partials: 4 parts max per (b, qtile)
__device__ float g_Opart[4 * 64 * 4 * 64 * 64];  // [b][qt][p][64*64] unnormalized
__device__ float g_m[4 * 64 * 4 * 64];
__device__ float g_l[4 * 64 * 4 * 64];

// ---------------------------------------------------------------------------
// Helpers
// ---------------------------------------------------------------------------
__device__ __forceinline__ unsigned f2tf(float f) {
    unsigned u;
    asm("cvt.rna.tf32.f32 %0, %1;" : "=r"(u) : "f"(f));
    return u;
}

__device__ __forceinline__ void mma_tf32(float* d, const unsigned* a, const unsigned* b) {
    asm volatile(
        "mma.sync.aligned.m16n8k8.row.col.f32.tf32.tf32.f32 "
        "{%0,%1,%2,%3}, {%4,%5,%6,%7}, {%8,%9}, {%0,%1,%2,%3};"
        : "+f"(d[0]), "+f"(d[1]), "+f"(d[2]), "+f"(d[3])
        : "r"(a[0]), "r"(a[1]), "r"(a[2]), "r"(a[3]), "r"(b[0]), "r"(b[1]));
}

__device__ __forceinline__ void cpa16(void* smem_dst, const void* gmem_src) {
    unsigned s = (unsigned)__cvta_generic_to_shared(smem_dst);
    asm volatile("cp.async.cg.shared.global [%0], [%1], 16;" :: "r"(s), "l"(gmem_src));
}
__device__ __forceinline__ void cpa_commit() { asm volatile("cp.async.commit_group;"); }

// ---------------------------------------------------------------------------
// Projection kernel (tensor cores, cp.async double buffered).
// 64 rows/block, 128 threads (4 warps), warp w -> rows w*16..w*16+15, all 64 cols,
// all three outputs. K dim in 32-wide stages.
// Epilogue converts results to tf32 (Q additionally pre-scaled by 0.125).
// ---------------------------------------------------------------------------
__global__ void __launch_bounds__(128) proj_kernel(
    const float* __restrict__ x,
    const float* __restrict__ Wq,
    const float* __restrict__ Wk,
    const float* __restrict__ Wv)
{
    extern __shared__ float sm[];
    // Xs[2][64][36], Ws[2][3][32][72]
    float (*Xs)[64][36] = reinterpret_cast<float(*)[64][36]>(sm);
    float (*Ws)[3][32][72] = reinterpret_cast<float(*)[3][32][72]>(sm + 2 * 64 * 36);

    const int tid = threadIdx.x;
    const int lane = tid & 31;
    const int warp = tid >> 5;
    const int g = lane >> 2;
    const int c = lane & 3;
    const int wrow = warp * 16;
    const int rowbase = blockIdx.x * 64;
    const float* Wsrc[3] = { Wq, Wk, Wv };

    float acc[3][8][4];
#pragma unroll
    for (int w = 0; w < 3; w++)
#pragma unroll
        for (int n = 0; n < 8; n++)
#pragma unroll
            for (int i = 0; i < 4; i++) acc[w][n][i] = 0.f;

    // Issue stage 0 loads
    auto issue_stage = [&](int s, int buf) {
        const int kb = s * 32;
#pragma unroll
        for (int t = tid; t < 512; t += 128) {           // X: 64 rows x 8 chunks
            int r = t >> 3, q4 = t & 7;
            cpa16(&Xs[buf][r][q4 * 4],
                  &x[(size_t)(rowbase + r) * D_ + kb + q4 * 4]);
        }
#pragma unroll
        for (int t = tid; t < 1536; t += 128) {          // W: 3 x 32 rows x 16 chunks
            int w = t >> 9;
            int rem = t & 511;
            int r = rem >> 4, q4 = rem & 15;
            cpa16(&Ws[buf][w][r][q4 * 4],
                  &Wsrc[w][(size_t)(kb + r) * H_ + q4 * 4]);
        }
        cpa_commit();
    };

    issue_stage(0, 0);

    for (int s = 0; s < 32; s++) {
        const int buf = s & 1;
        if (s < 31) issue_stage(s + 1, buf ^ 1);
        if (s < 31) { asm volatile("cp.async.wait_group 1;"); }
        else        { asm volatile("cp.async.wait_group 0;"); }
        __syncthreads();

#pragma unroll
        for (int k8 = 0; k8 < 4; k8++) {
            unsigned a[4];
            a[0] = f2tf(Xs[buf][wrow + g][k8 * 8 + c]);
            a[1] = f2tf(Xs[buf][wrow + g + 8][k8 * 8 + c]);
            a[2] = f2tf(Xs[buf][wrow + g][k8 * 8 + c + 4]);
            a[3] = f2tf(Xs[buf][wrow + g + 8][k8 * 8 + c + 4]);
#pragma unroll
            for (int w = 0; w < 3; w++)
#pragma unroll
                for (int n = 0; n < 8; n++) {
                    unsigned b[2] = { f2tf(Ws[buf][w][k8 * 8 + c][n * 8 + g]),
                                      f2tf(Ws[buf][w][k8 * 8 + c + 4][n * 8 + g]) };
                    mma_tf32(acc[w][n], a, b);
                }
        }
        __syncthreads();
    }

    // Epilogue: tf32-convert (Q pre-scaled) and write
#pragma unroll
    for (int n = 0; n < 8; n++) {
        size_t i0 = (size_t)(rowbase + wrow + g) * H_ + n * 8 + 2 * c;
        size_t i1 = i0 + (size_t)8 * H_;
        float2 q0 = make_float2(__uint_as_float(f2tf(acc[0][n][0] * 0.125f)),
                                __uint_as_float(f2tf(acc[0][n][1] * 0.125f)));
        float2 q1 = make_float2(__uint_as_float(f2tf(acc[0][n][2] * 0.125f)),
                                __uint_as_float(f2tf(acc[0][n][3] * 0.125f)));
        float2 k0 = make_float2(__uint_as_float(f2tf(acc[1][n][0])),
                                __uint_as_float(f2tf(acc[1][n][1])));
        float2 k1 = make_float2(__uint_as_float(f2tf(acc[1][n][2])),
                                __uint_as_float(f2tf(acc[1][n][3])));
        float2 v0 = make_float2(__uint_as_float(f2tf(acc[2][n][0])),
                                __uint_as_float(f2tf(acc[2][n][1])));
        float2 v1 = make_float2(__uint_as_float(f2tf(acc[2][n][2])),
                                __uint_as_float(f2tf(acc[2][n][3])));
        *reinterpret_cast<float2*>(&g_Q[i0]) = q0;
        *reinterpret_cast<float2*>(&g_Q[i1]) = q1;
        *reinterpret_cast<float2*>(&g_K[i0]) = k0;
        *reinterpret_cast<float2*>(&g_K[i1]) = k1;
        *reinterpret_cast<float2*>(&g_V[i0]) = v0;
        *reinterpret_cast<float2*>(&g_V[i1]) = v1;
    }
}

// ---------------------------------------------------------------------------
// Attention partial kernel (split-K causal flash attention, tf32 mma).
// grid (160, B): block bx -> (qtile, part); part p covers key tiles
// [16p, min(qt, 16p+15)]. Writes unnormalized O + (m, l) to scratch.
// 128 threads (4 warps), each warp owns 16 query rows.
// cp.async double-buffered K/V.
// ---------------------------------------------------------------------------
__global__ void __launch_bounds__(128) attn_partial_kernel()
{
    extern __shared__ float sm[];
    float (*Kb)[64][68] = reinterpret_cast<float(*)[64][68]>(sm);                 // [2]
    float (*Vb)[64][72] = reinterpret_cast<float(*)[64][72]>(sm + 2 * 64 * 68);   // [2]
    float (*Pb)[68]     = reinterpret_cast<float(*)[68]>(sm + 2 * 64 * 68 + 2 * 64 * 72);

    const int tid = threadIdx.x;
    const int lane = tid & 31;
    const int warp = tid >> 5;
    const int g = lane >> 2;
    const int c = lane & 3;
    const int wrow = warp * 16;
    const int b = blockIdx.y;

    // Map bx -> (qt, p)
    const int bx = blockIdx.x;
    int qt, p;
    if (bx < 16)      { qt = bx;                p = 0; }
    else if (bx < 48) { qt = 16 + (bx - 16) / 2; p = (bx - 16) % 2; }
    else if (bx < 96) { qt = 32 + (bx - 48) / 3; p = (bx - 48) % 3; }
    else              { qt = 48 + (bx - 96) / 4; p = (bx - 96) % 4; }

    const int k_lo = p * 16;
    const int k_hi = min(qt, k_lo + 15);
    const int q0 = qt * 64;
    const size_t qbase = (size_t)(b * T_ + q0) * H_;

    // Stage Q (already tf32 + pre-scaled) into Pb, read A fragments.
#pragma unroll
    for (int t = tid; t < 1024; t += 128) {
        int r = t >> 4, q4 = t & 15;
        *reinterpret_cast<float4*>(&Pb[r][q4 * 4]) =
            *reinterpret_cast<const float4*>(&g_Q[qbase + (size_t)r * H_ + q4 * 4]);
    }
    __syncthreads();

    unsigned qa[8][4];
#pragma unroll
    for (int k8 = 0; k8 < 8; k8++) {
        qa[k8][0] = __float_as_uint(Pb[wrow + g][k8 * 8 + c]);
        qa[k8][1] = __float_as_uint(Pb[wrow + g + 8][k8 * 8 + c]);
        qa[k8][2] = __float_as_uint(Pb[wrow + g][k8 * 8 + c + 4]);
        qa[k8][3] = __float_as_uint(Pb[wrow + g + 8][k8 * 8 + c + 4]);
    }

    auto issue_tile = [&](int kt, int buf) {
        const size_t kvbase = (size_t)(b * T_ + kt * 64) * H_;
#pragma unroll
        for (int t = tid; t < 1024; t += 128) {
            int r = t >> 4, q4 = t & 15;
            cpa16(&Kb[buf][r][q4 * 4],
                  &g_K[kvbase + (size_t)r * H_ + q4 * 4]);
            cpa16(&Vb[buf][r][q4 * 4],
                  &g_V[kvbase + (size_t)r * H_ + q4 * 4]);
        }
        cpa_commit();
    };

    float o[8][4];
#pragma unroll
    for (int n = 0; n < 8; n++)
#pragma unroll
        for (int i = 0; i < 4; i++) o[n][i] = 0.f;
    float m0 = -CUDART_INF_F, m1 = -CUDART_INF_F;
    float l0 = 0.f, l1 = 0.f;

    issue_tile(k_lo, k_lo & 1);

    for (int kt = k_lo; kt <= k_hi; kt++) {
        const int buf = kt & 1;
        if (kt < k_hi) issue_tile(kt + 1, buf ^ 1);
        if (kt < k_hi) { asm volatile("cp.async.wait_group 1;"); }
        else           { asm volatile("cp.async.wait_group 0;"); }
        __syncthreads();

        // S = Q K^T
        float s[8][4];
#pragma unroll
        for (int n = 0; n < 8; n++)
#pragma unroll
            for (int i = 0; i < 4; i++) s[n][i] = 0.f;
#pragma unroll
        for (int k8 = 0; k8 < 8; k8++)
#pragma unroll
            for (int n = 0; n < 8; n++) {
                unsigned bfr[2] = { __float_as_uint(Kb[buf][n * 8 + g][k8 * 8 + c]),
                                    __float_as_uint(Kb[buf][n * 8 + g][k8 * 8 + c + 4]) };
                mma_tf32(s[n], qa[k8], bfr);
            }

        // Causal mask on the diagonal tile
        if (kt == qt) {
            const int r0 = q0 + wrow + g;
            const int kb = kt * 64;
#pragma unroll
            for (int n = 0; n < 8; n++) {
                int col = kb + n * 8 + 2 * c;
                if (col     > r0)     s[n][0] = -CUDART_INF_F;
                if (col + 1 > r0)     s[n][1] = -CUDART_INF_F;
                if (col     > r0 + 8) s[n][2] = -CUDART_INF_F;
                if (col + 1 > r0 + 8) s[n][3] = -CUDART_INF_F;
            }
        }

        // Online softmax (per 16-row warp block; quad reductions)
        float mx0 = -CUDART_INF_F, mx1 = -CUDART_INF_F;
#pragma unroll
        for (int n = 0; n < 8; n++) {
            mx0 = fmaxf(mx0, fmaxf(s[n][0], s[n][1]));
            mx1 = fmaxf(mx1, fmaxf(s[n][2], s[n][3]));
        }
        mx0 = fmaxf(mx0, __shfl_xor_sync(0xffffffffu, mx0, 1));
        mx0 = fmaxf(mx0, __shfl_xor_sync(0xffffffffu, mx0, 2));
        mx1 = fmaxf(mx1, __shfl_xor_sync(0xffffffffu, mx1, 1));
        mx1 = fmaxf(mx1, __shfl_xor_sync(0xffffffffu, mx1, 2));

        const float mn0 = fmaxf(m0, mx0);
        const float mn1 = fmaxf(m1, mx1);
        const float al0 = __expf(m0 - mn0);
        const float al1 = __expf(m1 - mn1);

        float sum0 = 0.f, sum1 = 0.f;
#pragma unroll
        for (int n = 0; n < 8; n++) {
            float p00 = __expf(s[n][0] - mn0);
            float p01 = __expf(s[n][1] - mn0);
            float p10 = __expf(s[n][2] - mn1);
            float p11 = __expf(s[n][3] - mn1);
            sum0 += p00 + p01;
            sum1 += p10 + p11;
            uint2 u0; u0.x = f2tf(p00); u0.y = f2tf(p01);
            *reinterpret_cast<uint2*>(&Pb[wrow + g][n * 8 + 2 * c]) = u0;
            uint2 u1; u1.x = f2tf(p10); u1.y = f2tf(p11);
            *reinterpret_cast<uint2*>(&Pb[wrow + g + 8][n * 8 + 2 * c]) = u1;
            o[n][0] *= al0; o[n][1] *= al0;
            o[n][2] *= al1; o[n][3] *= al1;
        }
        sum0 += __shfl_xor_sync(0xffffffffu, sum0, 1);
        sum0 += __shfl_xor_sync(0xffffffffu, sum0, 2);
        sum1 += __shfl_xor_sync(0xffffffffu, sum1, 1);
        sum1 += __shfl_xor_sync(0xffffffffu, sum1, 2);
        l0 = l0 * al0 + sum0;
        l1 = l1 * al1 + sum1;
        m0 = mn0;
        m1 = mn1;
        __syncwarp();   // P visible within warp

        // O += P V
#pragma unroll
        for (int k8 = 0; k8 < 8; k8++) {
            unsigned a[4];
            a[0] = __float_as_uint(Pb[wrow + g][k8 * 8 + c]);
            a[1] = __float_as_uint(Pb[wrow + g + 8][k8 * 8 + c]);
            a[2] = __float_as_uint(Pb[wrow + g][k8 * 8 + c + 4]);
            a[3] = __float_as_uint(Pb[wrow + g + 8][k8 * 8 + c + 4]);
#pragma unroll
            for (int n = 0; n < 8; n++) {
                unsigned bfr[2] = { __float_as_uint(Vb[buf][k8 * 8 + c][n * 8 + g]),
                                    __float_as_uint(Vb[buf][k8 * 8 + c + 4][n * 8 + g]) };
                mma_tf32(o[n], a, bfr);
            }
        }
        __syncthreads();   // all warps done with buf before overwrite
    }

    // Write unnormalized partial + stats
    const int slot = ((b * 64 + qt) * 4 + p);
    float* Op = &g_Opart[(size_t)slot * 4096];
#pragma unroll
    for (int n = 0; n < 8; n++) {
        int i0 = (wrow + g) * 64 + n * 8 + 2 * c;
        int i1 = i0 + 8 * 64;
        *reinterpret_cast<float2*>(&Op[i0]) = make_float2(o[n][0], o[n][1]);
        *reinterpret_cast<float2*>(&Op[i1]) = make_float2(o[n][2], o[n][3]);
    }
    if (c == 0) {
        g_m[slot * 64 + wrow + g] = m0;
        g_m[slot * 64 + wrow + g + 8] = m1;
        g_l[slot * 64 + wrow + g] = l0;
        g_l[slot * 64 + wrow + g + 8] = l1;
    }
}

// ---------------------------------------------------------------------------
// Combine kernel: merge up to 4 partials per (b, qtile), normalize, write out.
// grid (64, B), 128 threads: thread -> (row = tid/2, 32-col half).
// ---------------------------------------------------------------------------
__global__ void __launch_bounds__(128) combine_kernel(float* __restrict__ out)
{
    const int qt = blockIdx.x;
    const int b = blockIdx.y;
    const int np = qt / 16 + 1;           // ceil((qt+1)/16)
    const int tid = threadIdx.x;
    const int r = tid >> 1;
    const int half = tid & 1;
    const int slot0 = (b * 64 + qt) * 4;

    float mmax = -CUDART_INF_F;
#pragma unroll
    for (int p = 0; p < 4; p++)
        if (p < np) mmax = fmaxf(mmax, g_m[(slot0 + p) * 64 + r]);

    float w[4];
    float lsum = 0.f;
#pragma unroll
    for (int p = 0; p < 4; p++) {
        if (p < np) {
            w[p] = __expf(g_m[(slot0 + p) * 64 + r] - mmax);
            lsum += w[p] * g_l[(slot0 + p) * 64 + r];
        } else w[p] = 0.f;
    }
    const float inv = 1.f / lsum;

    float acc[32];
#pragma unroll
    for (int i = 0; i < 32; i++) acc[i] = 0.f;
#pragma unroll
    for (int p = 0; p < 4; p++) {
        if (p < np) {
            const float* Op = &g_Opart[(size_t)(slot0 + p) * 4096 + r * 64 + half * 32];
#pragma unroll
            for (int i = 0; i < 8; i++) {
                float4 v = *reinterpret_cast<const float4*>(&Op[i * 4]);
                acc[i * 4 + 0] += w[p] * v.x;
                acc[i * 4 + 1] += w[p] * v.y;
                acc[i * 4 + 2] += w[p] * v.z;
                acc[i * 4 + 3] += w[p] * v.w;
            }
        }
    }

    float* op = &out[((size_t)(b * T_ + qt * 64 + r)) * H_ + half * 32];
#pragma unroll
    for (int i = 0; i < 8; i++) {
        float4 v = make_float4(acc[i * 4 + 0] * inv, acc[i * 4 + 1] * inv,
                               acc[i * 4 + 2] * inv, acc[i * 4 + 3] * inv);
        *reinterpret_cast<float4*>(&op[i * 4]) = v;
    }
}

// ---------------------------------------------------------------------------
static constexpr int PROJ_SMEM = (2 * 64 * 36 + 2 * 3 * 32 * 72) * 4;   // 73728
static constexpr int ATTN_SMEM = (2 * 64 * 68 + 2 * 64 * 72 + 64 * 68) * 4;  // 89088

extern "C" void kernel_launch(void* const* d_in, const int* in_sizes, int n_in,
                              void* d_out, int out_size)
{
    const float* x  = (const float*)d_in[0];
    const float* Wq = (const float*)d_in[1];
    const float* Wk = (const float*)d_in[2];
    const float* Wv = (const float*)d_in[3];
    float* out = (float*)d_out;

    cudaFuncSetAttribute(proj_kernel, cudaFuncAttributeMaxDynamicSharedMemorySize, PROJ_SMEM);
    cudaFuncSetAttribute(attn_partial_kernel, cudaFuncAttributeMaxDynamicSharedMemorySize, ATTN_SMEM);

    proj_kernel<<<BT / 64, 128, PROJ_SMEM>>>(x, Wq, Wk, Wv);
    attn_partial_kernel<<<dim3(160, B_), 128, ATTN_SMEM>>>();
    combine_kernel<<<dim3(64, B_), 128>>>(out);
}

// round 5
// speedup vs baseline: 8.0597x; 1.3472x over previous
#include <cuda_runtime.h>
#include <math_constants.h>

// Problem constants
static constexpr int B_ = 4;
static constexpr int T_ = 4096;
static constexpr int D_ = 1024;
static constexpr int H_ = 64;
static constexpr int BT = B_ * T_;

// Scratch (device globals: allocation-free per harness rules)
__device__ float g_Q[BT * H_];   // pre-scaled by 0.125 and tf32-rounded
__device__ float g_K[BT * H_];   // tf32-rounded
__device__ float g_V[BT * H_];   // tf32-rounded
__device__ float g_Wt[3 * D_ * H_];  // Wq|Wk|Wv pre-converted to tf32 bits

// Split-K attention partials: 4 parts max per (b, qtile)
__device__ float g_Opart[4 * 64 * 4 * 64 * 64];  // [b][qt][p][64*64] unnormalized
__device__ float g_m[4 * 64 * 4 * 64];
__device__ float g_l[4 * 64 * 4 * 64];

// ---------------------------------------------------------------------------
// Helpers
// ---------------------------------------------------------------------------
__device__ __forceinline__ unsigned f2tf(float f) {
    unsigned u;
    asm("cvt.rna.tf32.f32 %0, %1;" : "=r"(u) : "f"(f));
    return u;
}

__device__ __forceinline__ void mma_tf32(float* d, const unsigned* a, const unsigned* b) {
    asm volatile(
        "mma.sync.aligned.m16n8k8.row.col.f32.tf32.tf32.f32 "
        "{%0,%1,%2,%3}, {%4,%5,%6,%7}, {%8,%9}, {%0,%1,%2,%3};"
        : "+f"(d[0]), "+f"(d[1]), "+f"(d[2]), "+f"(d[3])
        : "r"(a[0]), "r"(a[1]), "r"(a[2]), "r"(a[3]), "r"(b[0]), "r"(b[1]));
}

__device__ __forceinline__ void mma_tf32u(unsigned* d4f, const unsigned* a, const unsigned* b) {
    mma_tf32(reinterpret_cast<float*>(d4f), a, b);
}

__device__ __forceinline__ void cpa16(void* smem_dst, const void* gmem_src) {
    unsigned s = (unsigned)__cvta_generic_to_shared(smem_dst);
    asm volatile("cp.async.cg.shared.global [%0], [%1], 16;" :: "r"(s), "l"(gmem_src));
}
__device__ __forceinline__ void cpa_commit() { asm volatile("cp.async.commit_group;"); }

// ---------------------------------------------------------------------------
// W pre-conversion: Wq|Wk|Wv (fp32) -> g_Wt (tf32 bits). 49152 float4 total.
// ---------------------------------------------------------------------------
__global__ void __launch_bounds__(256) precvt_kernel(
    const float* __restrict__ Wq,
    const float* __restrict__ Wk,
    const float* __restrict__ Wv)
{
    const int i = blockIdx.x * 256 + threadIdx.x;     // float4 index
    const int w = i >> 14;                            // /16384
    const int off = (i & 16383) << 2;
    const float* src = (w == 0) ? Wq : (w == 1) ? Wk : Wv;
    float4 v = *reinterpret_cast<const float4*>(&src[off]);
    float4 o;
    o.x = __uint_as_float(f2tf(v.x));
    o.y = __uint_as_float(f2tf(v.y));
    o.z = __uint_as_float(f2tf(v.z));
    o.w = __uint_as_float(f2tf(v.w));
    *reinterpret_cast<float4*>(&g_Wt[w * (D_ * H_) + off]) = o;
}

// ---------------------------------------------------------------------------
// Projection kernel: 64 rows x (3 x 64 cols) per block, 256 threads (8 warps).
// Warp layout: 4 row-warps (16 rows each) x 2 col-warps (32 cols each).
// cp.async double-buffered, k in 32-wide stages. X raw in smem (cvt at A-frag
// load only); W already tf32 (raw B-frag loads, zero cvt).
// ---------------------------------------------------------------------------
__global__ void __launch_bounds__(256, 2) proj_kernel(const float* __restrict__ x)
{
    extern __shared__ float sm[];
    float (*Xs)[64][36]     = reinterpret_cast<float(*)[64][36]>(sm);             // [2]
    float (*Ws)[3][32][72]  = reinterpret_cast<float(*)[3][32][72]>(sm + 2 * 64 * 36);

    const int tid = threadIdx.x;
    const int lane = tid & 31;
    const int warp = tid >> 5;
    const int g = lane >> 2;
    const int c = lane & 3;
    const int rw = (warp & 3) * 16;     // row offset within tile
    const int cw = warp >> 2;           // col half (0/1)
    const int rowbase = blockIdx.x * 64;

    float acc[3][4][4];
#pragma unroll
    for (int w = 0; w < 3; w++)
#pragma unroll
        for (int n = 0; n < 4; n++)
#pragma unroll
            for (int i = 0; i < 4; i++) acc[w][n][i] = 0.f;

    auto issue_stage = [&](int s, int buf) {
        const int kb = s * 32;
#pragma unroll
        for (int t = tid; t < 512; t += 256) {           // X: 64 rows x 8 chunks
            int r = t >> 3, q4 = t & 7;
            cpa16(&Xs[buf][r][q4 * 4],
                  &x[(size_t)(rowbase + r) * D_ + kb + q4 * 4]);
        }
#pragma unroll
        for (int t = tid; t < 1536; t += 256) {          // W: 3 x 32 rows x 16 chunks
            int w = t >> 9;
            int rem = t & 511;
            int r = rem >> 4, q4 = rem & 15;
            cpa16(&Ws[buf][w][r][q4 * 4],
                  &g_Wt[w * (D_ * H_) + (size_t)(kb + r) * H_ + q4 * 4]);
        }
        cpa_commit();
    };

    issue_stage(0, 0);

    for (int s = 0; s < 32; s++) {
        const int buf = s & 1;
        if (s < 31) { issue_stage(s + 1, buf ^ 1); asm volatile("cp.async.wait_group 1;"); }
        else        { asm volatile("cp.async.wait_group 0;"); }
        __syncthreads();

#pragma unroll
        for (int k8 = 0; k8 < 4; k8++) {
            unsigned a[4];
            a[0] = f2tf(Xs[buf][rw + g][k8 * 8 + c]);
            a[1] = f2tf(Xs[buf][rw + g + 8][k8 * 8 + c]);
            a[2] = f2tf(Xs[buf][rw + g][k8 * 8 + c + 4]);
            a[3] = f2tf(Xs[buf][rw + g + 8][k8 * 8 + c + 4]);
#pragma unroll
            for (int w = 0; w < 3; w++)
#pragma unroll
                for (int n = 0; n < 4; n++) {
                    const int nn = cw * 4 + n;
                    unsigned b[2] = {
                        __float_as_uint(Ws[buf][w][k8 * 8 + c][nn * 8 + g]),
                        __float_as_uint(Ws[buf][w][k8 * 8 + c + 4][nn * 8 + g]) };
                    mma_tf32(acc[w][n], a, b);
                }
        }
        __syncthreads();
    }

    // Epilogue: tf32-convert (Q pre-scaled by 0.125) and write
#pragma unroll
    for (int n = 0; n < 4; n++) {
        const int col = (cw * 4 + n) * 8 + 2 * c;
        size_t i0 = (size_t)(rowbase + rw + g) * H_ + col;
        size_t i1 = i0 + (size_t)8 * H_;
        float2 q0 = make_float2(__uint_as_float(f2tf(acc[0][n][0] * 0.125f)),
                                __uint_as_float(f2tf(acc[0][n][1] * 0.125f)));
        float2 q1 = make_float2(__uint_as_float(f2tf(acc[0][n][2] * 0.125f)),
                                __uint_as_float(f2tf(acc[0][n][3] * 0.125f)));
        float2 k0 = make_float2(__uint_as_float(f2tf(acc[1][n][0])),
                                __uint_as_float(f2tf(acc[1][n][1])));
        float2 k1 = make_float2(__uint_as_float(f2tf(acc[1][n][2])),
                                __uint_as_float(f2tf(acc[1][n][3])));
        float2 v0 = make_float2(__uint_as_float(f2tf(acc[2][n][0])),
                                __uint_as_float(f2tf(acc[2][n][1])));
        float2 v1 = make_float2(__uint_as_float(f2tf(acc[2][n][2])),
                                __uint_as_float(f2tf(acc[2][n][3])));
        *reinterpret_cast<float2*>(&g_Q[i0]) = q0;
        *reinterpret_cast<float2*>(&g_Q[i1]) = q1;
        *reinterpret_cast<float2*>(&g_K[i0]) = k0;
        *reinterpret_cast<float2*>(&g_K[i1]) = k1;
        *reinterpret_cast<float2*>(&g_V[i0]) = v0;
        *reinterpret_cast<float2*>(&g_V[i1]) = v1;
    }
}

// ---------------------------------------------------------------------------
// Attention partial kernel (split-K causal flash attention, tf32 mma).
// grid (160, B): block -> (qtile, part); part p covers key tiles
// [16p, min(qt, 16p+15)]. Writes unnormalized O + (m, l) to scratch.
// 128 threads (4 warps), each warp owns 16 query rows. cp.async double buffer.
// ---------------------------------------------------------------------------
__global__ void __launch_bounds__(128) attn_partial_kernel()
{
    extern __shared__ float sm[];
    float (*Kb)[64][68] = reinterpret_cast<float(*)[64][68]>(sm);                 // [2]
    float (*Vb)[64][72] = reinterpret_cast<float(*)[64][72]>(sm + 2 * 64 * 68);   // [2]
    float (*Pb)[68]     = reinterpret_cast<float(*)[68]>(sm + 2 * 64 * 68 + 2 * 64 * 72);

    const int tid = threadIdx.x;
    const int lane = tid & 31;
    const int warp = tid >> 5;
    const int g = lane >> 2;
    const int c = lane & 3;
    const int wrow = warp * 16;
    const int b = blockIdx.y;

    // Reverse order: long parts (high bx) start first.
    const int bx = gridDim.x - 1 - blockIdx.x;
    int qt, p;
    if (bx < 16)      { qt = bx;                 p = 0; }
    else if (bx < 48) { qt = 16 + (bx - 16) / 2; p = (bx - 16) % 2; }
    else if (bx < 96) { qt = 32 + (bx - 48) / 3; p = (bx - 48) % 3; }
    else              { qt = 48 + (bx - 96) / 4; p = (bx - 96) % 4; }

    const int k_lo = p * 16;
    const int k_hi = min(qt, k_lo + 15);
    const int q0 = qt * 64;
    const size_t qbase = (size_t)(b * T_ + q0) * H_;

    // Stage Q (already tf32 + pre-scaled) into Pb, read A fragments.
#pragma unroll
    for (int t = tid; t < 1024; t += 128) {
        int r = t >> 4, q4 = t & 15;
        *reinterpret_cast<float4*>(&Pb[r][q4 * 4]) =
            *reinterpret_cast<const float4*>(&g_Q[qbase + (size_t)r * H_ + q4 * 4]);
    }
    __syncthreads();

    unsigned qa[8][4];
#pragma unroll
    for (int k8 = 0; k8 < 8; k8++) {
        qa[k8][0] = __float_as_uint(Pb[wrow + g][k8 * 8 + c]);
        qa[k8][1] = __float_as_uint(Pb[wrow + g + 8][k8 * 8 + c]);
        qa[k8][2] = __float_as_uint(Pb[wrow + g][k8 * 8 + c + 4]);
        qa[k8][3] = __float_as_uint(Pb[wrow + g + 8][k8 * 8 + c + 4]);
    }

    auto issue_tile = [&](int kt, int buf) {
        const size_t kvbase = (size_t)(b * T_ + kt * 64) * H_;
#pragma unroll
        for (int t = tid; t < 1024; t += 128) {
            int r = t >> 4, q4 = t & 15;
            cpa16(&Kb[buf][r][q4 * 4], &g_K[kvbase + (size_t)r * H_ + q4 * 4]);
            cpa16(&Vb[buf][r][q4 * 4], &g_V[kvbase + (size_t)r * H_ + q4 * 4]);
        }
        cpa_commit();
    };

    float o[8][4];
#pragma unroll
    for (int n = 0; n < 8; n++)
#pragma unroll
        for (int i = 0; i < 4; i++) o[n][i] = 0.f;
    float m0 = -CUDART_INF_F, m1 = -CUDART_INF_F;
    float l0 = 0.f, l1 = 0.f;

    issue_tile(k_lo, k_lo & 1);

    for (int kt = k_lo; kt <= k_hi; kt++) {
        const int buf = kt & 1;
        if (kt < k_hi) { issue_tile(kt + 1, buf ^ 1); asm volatile("cp.async.wait_group 1;"); }
        else           { asm volatile("cp.async.wait_group 0;"); }
        __syncthreads();

        // S = Q K^T
        float s[8][4];
#pragma unroll
        for (int n = 0; n < 8; n++)
#pragma unroll
            for (int i = 0; i < 4; i++) s[n][i] = 0.f;
#pragma unroll
        for (int k8 = 0; k8 < 8; k8++)
#pragma unroll
            for (int n = 0; n < 8; n++) {
                unsigned bfr[2] = { __float_as_uint(Kb[buf][n * 8 + g][k8 * 8 + c]),
                                    __float_as_uint(Kb[buf][n * 8 + g][k8 * 8 + c + 4]) };
                mma_tf32(s[n], qa[k8], bfr);
            }

        // Causal mask on the diagonal tile
        if (kt == qt) {
            const int r0 = q0 + wrow + g;
            const int kb = kt * 64;
#pragma unroll
            for (int n = 0; n < 8; n++) {
                int col = kb + n * 8 + 2 * c;
                if (col     > r0)     s[n][0] = -CUDART_INF_F;
                if (col + 1 > r0)     s[n][1] = -CUDART_INF_F;
                if (col     > r0 + 8) s[n][2] = -CUDART_INF_F;
                if (col + 1 > r0 + 8) s[n][3] = -CUDART_INF_F;
            }
        }

        // Online softmax (per 16-row warp block; quad reductions)
        float mx0 = -CUDART_INF_F, mx1 = -CUDART_INF_F;
#pragma unroll
        for (int n = 0; n < 8; n++) {
            mx0 = fmaxf(mx0, fmaxf(s[n][0], s[n][1]));
            mx1 = fmaxf(mx1, fmaxf(s[n][2], s[n][3]));
        }
        mx0 = fmaxf(mx0, __shfl_xor_sync(0xffffffffu, mx0, 1));
        mx0 = fmaxf(mx0, __shfl_xor_sync(0xffffffffu, mx0, 2));
        mx1 = fmaxf(mx1, __shfl_xor_sync(0xffffffffu, mx1, 1));
        mx1 = fmaxf(mx1, __shfl_xor_sync(0xffffffffu, mx1, 2));

        const float mn0 = fmaxf(m0, mx0);
        const float mn1 = fmaxf(m1, mx1);
        const float al0 = __expf(m0 - mn0);
        const float al1 = __expf(m1 - mn1);

        float sum0 = 0.f, sum1 = 0.f;
#pragma unroll
        for (int n = 0; n < 8; n++) {
            float p00 = __expf(s[n][0] - mn0);
            float p01 = __expf(s[n][1] - mn0);
            float p10 = __expf(s[n][2] - mn1);
            float p11 = __expf(s[n][3] - mn1);
            sum0 += p00 + p01;
            sum1 += p10 + p11;
            uint2 u0; u0.x = f2tf(p00); u0.y = f2tf(p01);
            *reinterpret_cast<uint2*>(&Pb[wrow + g][n * 8 + 2 * c]) = u0;
            uint2 u1; u1.x = f2tf(p10); u1.y = f2tf(p11);
            *reinterpret_cast<uint2*>(&Pb[wrow + g + 8][n * 8 + 2 * c]) = u1;
            o[n][0] *= al0; o[n][1] *= al0;
            o[n][2] *= al1; o[n][3] *= al1;
        }
        sum0 += __shfl_xor_sync(0xffffffffu, sum0, 1);
        sum0 += __shfl_xor_sync(0xffffffffu, sum0, 2);
        sum1 += __shfl_xor_sync(0xffffffffu, sum1, 1);
        sum1 += __shfl_xor_sync(0xffffffffu, sum1, 2);
        l0 = l0 * al0 + sum0;
        l1 = l1 * al1 + sum1;
        m0 = mn0;
        m1 = mn1;
        __syncwarp();   // P visible within warp

        // O += P V
#pragma unroll
        for (int k8 = 0; k8 < 8; k8++) {
            unsigned a[4];
            a[0] = __float_as_uint(Pb[wrow + g][k8 * 8 + c]);
            a[1] = __float_as_uint(Pb[wrow + g + 8][k8 * 8 + c]);
            a[2] = __float_as_uint(Pb[wrow + g][k8 * 8 + c + 4]);
            a[3] = __float_as_uint(Pb[wrow + g + 8][k8 * 8 + c + 4]);
#pragma unroll
            for (int n = 0; n < 8; n++) {
                unsigned bfr[2] = { __float_as_uint(Vb[buf][k8 * 8 + c][n * 8 + g]),
                                    __float_as_uint(Vb[buf][k8 * 8 + c + 4][n * 8 + g]) };
                mma_tf32(o[n], a, bfr);
            }
        }
        __syncthreads();   // all warps done with buf before overwrite
    }

    // Write unnormalized partial + stats
    const int slot = ((b * 64 + qt) * 4 + p);
    float* Op = &g_Opart[(size_t)slot * 4096];
#pragma unroll
    for (int n = 0; n < 8; n++) {
        int i0 = (wrow + g) * 64 + n * 8 + 2 * c;
        int i1 = i0 + 8 * 64;
        *reinterpret_cast<float2*>(&Op[i0]) = make_float2(o[n][0], o[n][1]);
        *reinterpret_cast<float2*>(&Op[i1]) = make_float2(o[n][2], o[n][3]);
    }
    if (c == 0) {
        g_m[slot * 64 + wrow + g] = m0;
        g_m[slot * 64 + wrow + g + 8] = m1;
        g_l[slot * 64 + wrow + g] = l0;
        g_l[slot * 64 + wrow + g + 8] = l1;
    }
}

// ---------------------------------------------------------------------------
// Combine kernel: merge up to 4 partials per (b, qtile), normalize, write out.
// ---------------------------------------------------------------------------
__global__ void __launch_bounds__(128) combine_kernel(float* __restrict__ out)
{
    const int qt = blockIdx.x;
    const int b = blockIdx.y;
    const int np = qt / 16 + 1;
    const int tid = threadIdx.x;
    const int r = tid >> 1;
    const int half = tid & 1;
    const int slot0 = (b * 64 + qt) * 4;

    float mmax = -CUDART_INF_F;
#pragma unroll
    for (int p = 0; p < 4; p++)
        if (p < np) mmax = fmaxf(mmax, g_m[(slot0 + p) * 64 + r]);

    float w[4];
    float lsum = 0.f;
#pragma unroll
    for (int p = 0; p < 4; p++) {
        if (p < np) {
            w[p] = __expf(g_m[(slot0 + p) * 64 + r] - mmax);
            lsum += w[p] * g_l[(slot0 + p) * 64 + r];
        } else w[p] = 0.f;
    }
    const float inv = 1.f / lsum;

    float acc[32];
#pragma unroll
    for (int i = 0; i < 32; i++) acc[i] = 0.f;
#pragma unroll
    for (int p = 0; p < 4; p++) {
        if (p < np) {
            const float* Op = &g_Opart[(size_t)(slot0 + p) * 4096 + r * 64 + half * 32];
#pragma unroll
            for (int i = 0; i < 8; i++) {
                float4 v = *reinterpret_cast<const float4*>(&Op[i * 4]);
                acc[i * 4 + 0] += w[p] * v.x;
                acc[i * 4 + 1] += w[p] * v.y;
                acc[i * 4 + 2] += w[p] * v.z;
                acc[i * 4 + 3] += w[p] * v.w;
            }
        }
    }

    float* op = &out[((size_t)(b * T_ + qt * 64 + r)) * H_ + half * 32];
#pragma unroll
    for (int i = 0; i < 8; i++) {
        float4 v = make_float4(acc[i * 4 + 0] * inv, acc[i * 4 + 1] * inv,
                               acc[i * 4 + 2] * inv, acc[i * 4 + 3] * inv);
        *reinterpret_cast<float4*>(&op[i * 4]) = v;
    }
}

// ---------------------------------------------------------------------------
static constexpr int PROJ_SMEM = (2 * 64 * 36 + 2 * 3 * 32 * 72) * 4;        // 73728
static constexpr int ATTN_SMEM = (2 * 64 * 68 + 2 * 64 * 72 + 64 * 68) * 4;  // 89088

extern "C" void kernel_launch(void* const* d_in, const int* in_sizes, int n_in,
                              void* d_out, int out_size)
{
    const float* x  = (const float*)d_in[0];
    const float* Wq = (const float*)d_in[1];
    const float* Wk = (const float*)d_in[2];
    const float* Wv = (const float*)d_in[3];
    float* out = (float*)d_out;

    cudaFuncSetAttribute(proj_kernel, cudaFuncAttributeMaxDynamicSharedMemorySize, PROJ_SMEM);
    cudaFuncSetAttribute(attn_partial_kernel, cudaFuncAttributeMaxDynamicSharedMemorySize, ATTN_SMEM);

    precvt_kernel<<<192, 256>>>(Wq, Wk, Wv);
    proj_kernel<<<BT / 64, 256, PROJ_SMEM>>>(x);
    attn_partial_kernel<<<dim3(160, B_), 128, ATTN_SMEM>>>();
    combine_kernel<<<dim3(64, B_), 128>>>(out);
}